// round 1
// baseline (speedup 1.0000x reference)
#include <cuda_runtime.h>

#define N_TOKENS 131072
#define HIDDEN   2048
#define N_RANKS  8
#define N_EXPERTS 16
#define N_SEG    (N_RANKS * N_EXPERTS)
#define VEC      (HIDDEN / 4)   // 512 float4 per row

// scratch (no cudaMalloc allowed)
__device__ int g_src[N_TOKENS];     // source row for each output row
__device__ int g_in_off[N_SEG];     // input offset of segment s = r*E + e
__device__ int g_out_off[N_SEG];    // output offset of segment s = r*E + e
__device__ int g_count[N_SEG];

// ---------------------------------------------------------------------------
// Kernel 1: tiny serial scan over the 128 segment counts.
// Input layout is rank-major, expert-minor (seg = r*E + e).
// Output layout is expert-major, rank-minor (for e: for r: segment (r,e)).
// Also writes per-expert totals (as float) to the output tail.
// ---------------------------------------------------------------------------
__global__ void compute_offsets(const int* __restrict__ counts,
                                float* __restrict__ out_expert_num) {
    if (threadIdx.x == 0 && blockIdx.x == 0) {
        int in_off = 0;
        #pragma unroll 1
        for (int s = 0; s < N_SEG; s++) {
            g_in_off[s] = in_off;
            int c = counts[s];
            g_count[s] = c;
            in_off += c;
        }
        int out_off = 0;
        #pragma unroll 1
        for (int e = 0; e < N_EXPERTS; e++) {
            int tot = 0;
            #pragma unroll 1
            for (int r = 0; r < N_RANKS; r++) {
                int s = r * N_EXPERTS + e;
                g_out_off[s] = out_off;
                out_off += g_count[s];
                tot += g_count[s];
            }
            out_expert_num[e] = (float)tot;
        }
    }
}

// ---------------------------------------------------------------------------
// Kernel 2: per-segment fill of the source-row map, permuted scales, and the
// idx output (written as float, values < 2^24 so exact).
// ---------------------------------------------------------------------------
__global__ void build_idx(const float* __restrict__ scales,
                          float* __restrict__ out_scales,
                          float* __restrict__ out_idx) {
    int s = blockIdx.x;                 // segment in input indexing (r*E + e)
    int in0  = g_in_off[s];
    int out0 = g_out_off[s];
    int n    = g_count[s];
    for (int j = threadIdx.x; j < n; j += blockDim.x) {
        int src = in0 + j;
        int dst = out0 + j;
        g_src[dst]      = src;
        out_scales[dst] = scales[src];
        out_idx[dst]    = (float)src;
    }
}

// ---------------------------------------------------------------------------
// Kernel 3: the heavy gather copy. One block per output row; each gathered
// row is 8 KiB contiguous, so both read and write are fully coalesced.
// ---------------------------------------------------------------------------
__global__ void __launch_bounds__(512)
gather_rows(const float4* __restrict__ in, float4* __restrict__ out) {
    int row = blockIdx.x;
    int src = g_src[row];
    const float4* __restrict__ s = in  + (size_t)src * VEC;
    float4* __restrict__ d       = out + (size_t)row * VEC;
    d[threadIdx.x] = s[threadIdx.x];
}

extern "C" void kernel_launch(void* const* d_in, const int* in_sizes, int n_in,
                              void* d_out, int out_size) {
    const float* tokens = (const float*)d_in[0];  // [N_TOKENS, HIDDEN] f32
    const int*   counts = (const int*)d_in[1];    // [N_RANKS, N_EXPERTS] i32
    const float* scales = (const float*)d_in[2];  // [N_TOKENS] f32
    // d_in[3] = expert_token_num_type (1 = counts), d_in[4] = idx_type (0) — fixed here.

    float* out        = (float*)d_out;
    float* out_tokens = out;                                   // N_TOKENS*HIDDEN
    float* out_scales = out + (size_t)N_TOKENS * HIDDEN;       // N_TOKENS
    float* out_idx    = out_scales + N_TOKENS;                 // N_TOKENS
    float* out_enum   = out_idx + N_TOKENS;                    // N_EXPERTS

    compute_offsets<<<1, 32>>>(counts, out_enum);
    build_idx<<<N_SEG, 256>>>(scales, out_scales, out_idx);
    gather_rows<<<N_TOKENS, 512>>>((const float4*)tokens, (float4*)out_tokens);
}

// round 3
// speedup vs baseline: 1.2785x; 1.2785x over previous
#include <cuda_runtime.h>

#define N_TOKENS  131072
#define HIDDEN    2048
#define N_RANKS   8
#define N_EXPERTS 16
#define N_SEG     (N_RANKS * N_EXPERTS)
#define VEC       (HIDDEN / 4)       // 512 float4 per row
#define ROWS_PER_BLK 4

// scratch (no cudaMalloc allowed)
__device__ int g_src[N_TOKENS];      // source row for each output row
__device__ int g_in_off[N_SEG];
__device__ int g_out_off[N_SEG];
__device__ int g_count[N_SEG];

// ---------------------------------------------------------------------------
// Kernel 1: parallel 128-wide scan over segment counts, both orderings.
// seg s = r*E + e (input order). Output order position p = e*R + r.
// ---------------------------------------------------------------------------
__global__ void compute_offsets(const int* __restrict__ counts,
                                float* __restrict__ out_expert_num) {
    __shared__ int c[N_SEG];
    __shared__ int a[N_SEG];   // inclusive scan, input order
    __shared__ int b[N_SEG];   // inclusive scan, output order
    int t = threadIdx.x;       // 0..127
    c[t] = counts[t];
    __syncthreads();
    // b scans counts reordered to output order: position p -> seg (p%R)*E + p/R
    a[t] = c[t];
    b[t] = c[(t % N_RANKS) * N_EXPERTS + (t / N_RANKS)];
    __syncthreads();
    #pragma unroll
    for (int d = 1; d < N_SEG; d <<= 1) {
        int x = (t >= d) ? a[t - d] : 0;
        int y = (t >= d) ? b[t - d] : 0;
        __syncthreads();
        a[t] += x;
        b[t] += y;
        __syncthreads();
    }
    g_in_off[t] = a[t] - c[t];
    // seg t = r*E + e sits at output position p = e*R + r; b[p] includes c[t]
    int r = t / N_EXPERTS, e = t % N_EXPERTS;
    int p = e * N_RANKS + r;
    g_out_off[t] = b[p] - c[t];
    g_count[t] = c[t];
    if (t < N_EXPERTS) {
        int tot = 0;
        #pragma unroll
        for (int rr = 0; rr < N_RANKS; rr++) tot += c[rr * N_EXPERTS + t];
        out_expert_num[t] = (float)tot;
    }
}

// ---------------------------------------------------------------------------
// Kernel 2: per-segment fill of source map, permuted scales, idx (as float).
// ---------------------------------------------------------------------------
__global__ void build_idx(const float* __restrict__ scales,
                          float* __restrict__ out_scales,
                          float* __restrict__ out_idx) {
    int s = blockIdx.x;
    int in0  = g_in_off[s];
    int out0 = g_out_off[s];
    int n    = g_count[s];
    for (int j = threadIdx.x; j < n; j += blockDim.x) {
        int src = in0 + j;
        int dst = out0 + j;
        g_src[dst]      = src;
        out_scales[dst] = scales[src];
        out_idx[dst]    = (float)src;
    }
}

// ---------------------------------------------------------------------------
// Kernel 3: heavy gather. 4 rows per block -> 4 independent float4 loads in
// flight per thread before the 4 stores. Streaming hints: zero reuse.
// ---------------------------------------------------------------------------
__global__ void __launch_bounds__(512)
gather_rows(const float4* __restrict__ in, float4* __restrict__ out) {
    int base = blockIdx.x * ROWS_PER_BLK;
    int t = threadIdx.x;
    int s0 = g_src[base + 0];
    int s1 = g_src[base + 1];
    int s2 = g_src[base + 2];
    int s3 = g_src[base + 3];
    float4 a0 = __ldcs(in + (size_t)s0 * VEC + t);
    float4 a1 = __ldcs(in + (size_t)s1 * VEC + t);
    float4 a2 = __ldcs(in + (size_t)s2 * VEC + t);
    float4 a3 = __ldcs(in + (size_t)s3 * VEC + t);
    float4* d = out + (size_t)base * VEC + t;
    __stcs(d + 0 * VEC, a0);
    __stcs(d + 1 * VEC, a1);
    __stcs(d + 2 * VEC, a2);
    __stcs(d + 3 * VEC, a3);
}

extern "C" void kernel_launch(void* const* d_in, const int* in_sizes, int n_in,
                              void* d_out, int out_size) {
    const float* tokens = (const float*)d_in[0];  // [N_TOKENS, HIDDEN] f32
    const int*   counts = (const int*)d_in[1];    // [N_RANKS, N_EXPERTS] i32
    const float* scales = (const float*)d_in[2];  // [N_TOKENS] f32

    float* out        = (float*)d_out;
    float* out_tokens = out;                                   // N_TOKENS*HIDDEN
    float* out_scales = out + (size_t)N_TOKENS * HIDDEN;       // N_TOKENS
    float* out_idx    = out_scales + N_TOKENS;                 // N_TOKENS
    float* out_enum   = out_idx + N_TOKENS;                    // N_EXPERTS

    compute_offsets<<<1, N_SEG>>>(counts, out_enum);
    build_idx<<<N_SEG, 256>>>(scales, out_scales, out_idx);
    gather_rows<<<N_TOKENS / ROWS_PER_BLK, 512>>>((const float4*)tokens,
                                                  (float4*)out_tokens);
}